// round 9
// baseline (speedup 1.0000x reference)
#include <cuda_runtime.h>
#include <cuda_bf16.h>
#include <math.h>

// Problem constants
#define NQ   10
#define DIM  1024        // 2^NQ
#define NT   32
#define DM   512
#define NB   128         // batch
#define NPQC 40
#define NSIM (NB * NT)   // 4096 statevector sims per pass

// ---------------- device scratch (static globals, no allocation) -------------
__device__ float2 d_part1[(size_t)NB * 4 * DIM]; // pass-1 per-CTA LCU partials (4 MB)
__device__ float2 d_part2[(size_t)NB * 4 * DIM]; // pass-2 per-CTA LCU partials (4 MB)
__device__ float2 d_gt[(size_t)NSIM * NPQC];     // per-(b,l) gate (cos,sin) tables
__device__ float2 d_lcuW[NT];                    // normalized LCU weights

// Gate encoding: bit0 = type (0=RY, 1=CRX); bits[1..4] = RY bit position or
// CRX control position; bits[5..8] = CRX target position.
// Bit position p of qubit wire w is p = 9 - w (reference is big-endian).
#define RYG(p)      ((unsigned)((p) << 1))
#define CXG(cp, tp) ((unsigned)(1u | ((cp) << 1) | ((tp) << 5)))

#define GATE_LIST                                                              \
        RYG(9), RYG(8), RYG(7), RYG(6), RYG(5), RYG(4), RYG(3), RYG(2),        \
        RYG(1), RYG(0),                                                        \
        CXG(0, 9), CXG(1, 0), CXG(2, 1), CXG(3, 2), CXG(4, 3),                 \
        CXG(5, 4), CXG(6, 5), CXG(7, 6), CXG(8, 7), CXG(9, 8),                 \
        RYG(9), RYG(8), RYG(7), RYG(6), RYG(5), RYG(4), RYG(3), RYG(2),        \
        RYG(1), RYG(0),                                                        \
        CXG(0, 1), CXG(9, 0), CXG(8, 9), CXG(7, 8), CXG(6, 7),                 \
        CXG(5, 6), CXG(4, 5), CXG(3, 4), CXG(2, 3), CXG(1, 2)

// ---- register-resident circuit: lane L slot r holds amplitude g = r*32+L ----
//   g bits 5..9 -> register bits (pure-FFMA butterflies)
//   g bits 0..4 -> lane bits (partner via shfl.xor; controls fold into coeffs)
__device__ __forceinline__ void apply_circuit_reg(float2 a[32],
                                                  const float2* __restrict__ g,
                                                  int L)
{
    constexpr unsigned G[NPQC] = { GATE_LIST };
#pragma unroll
    for (int k = 0; k < NPQC; ++k) {
        const unsigned e = G[k];
        const float cth = g[k].x;
        const float sth = g[k].y;
        if (!(e & 1u)) {
            const int p = (int)((e >> 1) & 15u);
            if (p >= 5) {
                // RY on register bit
                const int rb = 1 << (p - 5);
#pragma unroll
                for (int r0 = 0; r0 < 32; ++r0) {
                    if (!(r0 & rb)) {
                        const int r1 = r0 | rb;
                        const float2 a0 = a[r0], a1 = a[r1];
                        a[r0] = make_float2(cth * a0.x - sth * a1.x,
                                            cth * a0.y - sth * a1.y);
                        a[r1] = make_float2(sth * a0.x + cth * a1.x,
                                            sth * a0.y + cth * a1.y);
                    }
                }
            } else {
                // RY on lane bit: a' = c*a + se*partner, se = bit? +s : -s
                const int lb = 1 << p;
                const float se = (L & lb) ? sth : -sth;
#pragma unroll
                for (int r = 0; r < 32; ++r) {
                    const float px = __shfl_xor_sync(0xffffffffu, a[r].x, lb);
                    const float py = __shfl_xor_sync(0xffffffffu, a[r].y, lb);
                    a[r] = make_float2(cth * a[r].x + se * px,
                                       cth * a[r].y + se * py);
                }
            }
        } else {
            const int cp = (int)((e >> 1) & 15u);
            const int tp = (int)((e >> 5) & 15u);
            if (tp >= 5) {
                const int rb = 1 << (tp - 5);
                if (cp >= 5) {
                    // control is a register bit: folds at compile time
                    const int cb = 1 << (cp - 5);
#pragma unroll
                    for (int r0 = 0; r0 < 32; ++r0) {
                        if (!(r0 & rb) && (r0 & cb)) {
                            const int r1 = r0 | rb;
                            const float2 a0 = a[r0], a1 = a[r1];
                            a[r0] = make_float2(cth * a0.x + sth * a1.y,
                                                cth * a0.y - sth * a1.x);
                            a[r1] = make_float2(sth * a0.y + cth * a1.x,
                                                cth * a1.y - sth * a0.x);
                        }
                    }
                } else {
                    // lane-bit control folded into coefficients
                    const bool act = (L >> cp) & 1;
                    const float ce = act ? cth : 1.f;
                    const float se = act ? sth : 0.f;
#pragma unroll
                    for (int r0 = 0; r0 < 32; ++r0) {
                        if (!(r0 & rb)) {
                            const int r1 = r0 | rb;
                            const float2 a0 = a[r0], a1 = a[r1];
                            a[r0] = make_float2(ce * a0.x + se * a1.y,
                                                ce * a0.y - se * a1.x);
                            a[r1] = make_float2(se * a0.y + ce * a1.x,
                                                ce * a1.y - se * a0.x);
                        }
                    }
                }
            } else {
                // RX on lane bit: a' = (c*ax + s*py, c*ay - s*px)
                const int lb = 1 << tp;
                if (cp >= 5) {
                    const int cb = 1 << (cp - 5);
#pragma unroll
                    for (int r = 0; r < 32; ++r) {
                        if (r & cb) {
                            const float px = __shfl_xor_sync(0xffffffffu, a[r].x, lb);
                            const float py = __shfl_xor_sync(0xffffffffu, a[r].y, lb);
                            a[r] = make_float2(cth * a[r].x + sth * py,
                                               cth * a[r].y - sth * px);
                        }
                    }
                } else {
                    const bool act = (L >> cp) & 1;
                    const float ce = act ? cth : 1.f;
                    const float se = act ? sth : 0.f;
#pragma unroll
                    for (int r = 0; r < 32; ++r) {
                        const float px = __shfl_xor_sync(0xffffffffu, a[r].x, lb);
                        const float py = __shfl_xor_sync(0xffffffffu, a[r].y, lb);
                        a[r] = make_float2(ce * a[r].x + se * py,
                                           ce * a[r].y - se * px);
                    }
                }
            }
        }
    }
}

// ----------------------------- kernels --------------------------------------

// pqc_params = tokens @ W.T + b -> (cos, sin) of theta/2 per gate.
// 512 blocks x 256 threads; each block handles 8 token rows so every W row is
// read once per block (W L2 traffic 320 MB -> 40 MB).
// Block 0 additionally computes the normalized LCU weights (warp 0).
__global__ void __launch_bounds__(256) params_kernel(
    const float* __restrict__ tokens,
    const float* __restrict__ W,
    const float* __restrict__ bias,
    const float* __restrict__ lre,
    const float* __restrict__ lim)
{
    const int row0 = blockIdx.x * 8;            // first (b*32+l) row
    const int tid  = threadIdx.x;

    if (blockIdx.x == 0 && tid < 32) {
        const float r = lre[tid], i = lim[tid];
        const float aa = sqrtf(r * r + i * i);
        float ssum = aa;
#pragma unroll
        for (int o = 16; o; o >>= 1) ssum += __shfl_xor_sync(0xffffffffu, ssum, o);
        d_lcuW[tid] = make_float2(r / ssum, i / ssum);
    }

    __shared__ float4 sh4[8][DM / 4];           // 8 rows x 128 float4 = 16 KB
    {
        const float4* t4 = (const float4*)(tokens + (size_t)row0 * DM);
#pragma unroll
        for (int i = tid; i < 8 * (DM / 4); i += 256)
            sh4[i >> 7][i & 127] = t4[i];
    }
    __syncthreads();

    const int warp = tid >> 5;
    const int lane = tid & 31;
    for (int k = warp; k < NPQC; k += 8) {
        // load W[k] once per warp: 16 floats per lane
        float4 wv[4];
        const float4* w4 = (const float4*)(W + (size_t)k * DM);
#pragma unroll
        for (int j = 0; j < 4; ++j) wv[j] = __ldg(w4 + lane + j * 32);
        const float bk = __ldg(bias + k);

#pragma unroll
        for (int row = 0; row < 8; ++row) {
            float acc = 0.f;
#pragma unroll
            for (int j = 0; j < 4; ++j) {
                const float4 t = sh4[row][lane + j * 32];
                acc += t.x * wv[j].x + t.y * wv[j].y +
                       t.z * wv[j].z + t.w * wv[j].w;
            }
#pragma unroll
            for (int o = 16; o; o >>= 1) acc += __shfl_xor_sync(0xffffffffu, acc, o);
            if (lane == 0) {
                const float h = 0.5f * (acc + bk);
                d_gt[(size_t)(row0 + row) * NPQC + k] = make_float2(cosf(h), sinf(h));
            }
        }
    }
}

// Warp-per-statevector simulator. One CTA = 8 warps = 8 consecutive l-values
// of one batch. Pass 2 rebuilds the monomial state from the 4 pass-1 partials
// (smem-staged, summed once per CTA). The LCU-weighted sum over the CTA's 8
// l's is reduced in smem and written to the pass's partial buffer.
template <bool FIRST>
__global__ void __launch_bounds__(256, 2) wsim_kernel()
{
    const int blk = blockIdx.x;          // b*4 + c
    const int b   = blk >> 2;
    const int c   = blk & 3;
    const int tid = threadIdx.x;         // 256
    const int w   = tid >> 5;            // warp 0..7
    const int L   = tid & 31;
    const int l   = c * 8 + w;

    __shared__ float2 sg[8][NPQC];       // gate tables (2.5 KB)
    __shared__ float2 sbuf[4][DIM];      // staging / reduction slots (32 KB)

    // Load 8 gate tables (contiguous in d_gt) cooperatively.
    {
        const float2* gbase = d_gt + ((size_t)(b * NT + c * 8)) * NPQC;
        for (int i = tid; i < 8 * NPQC; i += 256)
            (&sg[0][0])[i] = gbase[i];
    }

    if (!FIRST) {
        // mono = sum of the batch's 4 pass-1 partials; stage in sbuf[0].
        for (int g = tid; g < DIM; g += 256) {
            float2 m = d_part1[(size_t)(b * 4 + 0) * DIM + g];
#pragma unroll
            for (int cc = 1; cc < 4; ++cc) {
                const float2 v = d_part1[(size_t)(b * 4 + cc) * DIM + g];
                m.x += v.x; m.y += v.y;
            }
            sbuf[0][g] = m;
        }
    }
    __syncthreads();

    float2 a[32];
    if (FIRST) {
#pragma unroll
        for (int r = 0; r < 32; ++r) a[r] = make_float2(0.f, 0.f);
        a[0].x = (L == 0) ? 1.f : 0.f;
    } else {
#pragma unroll
        for (int r = 0; r < 32; ++r) a[r] = sbuf[0][r * 32 + L];
    }
    __syncthreads();   // sbuf[0] reads complete before epilogue reuses sbuf

    apply_circuit_reg(a, sg[w], L);

    // ---- LCU weight + in-CTA reduction over the 8 warps --------------------
    const float2 wl = d_lcuW[l];
#pragma unroll
    for (int r = 0; r < 32; ++r) {
        const float2 v = a[r];
        a[r] = make_float2(wl.x * v.x - wl.y * v.y,
                           wl.x * v.y + wl.y * v.x);
    }
    // stage 1: warps 0-3 write their weighted state to slot w
    if (w < 4) {
#pragma unroll
        for (int r = 0; r < 32; ++r) sbuf[w][r * 32 + L] = a[r];
    }
    __syncthreads();
    // stage 2: warps 4-7 add into slot w-4
    if (w >= 4) {
        const int slot = w - 4;
#pragma unroll
        for (int r = 0; r < 32; ++r) {
            float2 v = sbuf[slot][r * 32 + L];
            v.x += a[r].x; v.y += a[r].y;
            sbuf[slot][r * 32 + L] = v;
        }
    }
    __syncthreads();
    // stage 3: 256 threads reduce the 4 slots, write the CTA partial
    float2* outp = (FIRST ? d_part1 : d_part2) + (size_t)blk * DIM;
#pragma unroll
    for (int j = 0; j < 4; ++j) {
        const int g = tid + j * 256;
        float2 m = sbuf[0][g];
#pragma unroll
        for (int wi = 1; wi < 4; ++wi) {
            m.x += sbuf[wi][g].x;
            m.y += sbuf[wi][g].y;
        }
        outp[g] = m;
    }
}

// Warp-per-batch final stage: QSVT-combine partials into a register state,
// normalize, apply feed-forward ansatz, measure X/Y/Z. 16 CTAs x 8 warps.
__global__ void __launch_bounds__(256) final_kernel(const float* __restrict__ qsvt,
                                                    const float* __restrict__ ffp,
                                                    float* __restrict__ out)
{
    const int tid = threadIdx.x;
    const int w   = tid >> 5;
    const int L   = tid & 31;
    const int b   = blockIdx.x * 8 + w;          // batch index, 0..127

    __shared__ float2 sgf[NPQC];                 // feed-forward gate table
    if (tid < NPQC) {
        const float h = 0.5f * ffp[tid];
        sgf[tid] = make_float2(cosf(h), sinf(h));
    }
    __syncthreads();

    const float c0 = qsvt[0], c1 = qsvt[1], c2 = qsvt[2];

    // QSVT accumulator in registers (scale 1/sum|qsvt| cancels in normalize)
    float2 a[32];
#pragma unroll
    for (int r = 0; r < 32; ++r) {
        const int g = r * 32 + L;
        float2 m1 = make_float2(0.f, 0.f), m2 = make_float2(0.f, 0.f);
#pragma unroll
        for (int c = 0; c < 4; ++c) {
            const size_t base = (size_t)(b * 4 + c) * DIM + g;
            const float2 v1 = d_part1[base];
            const float2 v2 = d_part2[base];
            m1.x += v1.x; m1.y += v1.y;
            m2.x += v2.x; m2.y += v2.y;
        }
        a[r] = make_float2(c1 * m1.x + c2 * m2.x, c1 * m1.y + c2 * m2.y);
    }
    if (L == 0) a[0].x += c0;

    // in-warp L2 normalization
    float nn = 0.f;
#pragma unroll
    for (int r = 0; r < 32; ++r) nn += a[r].x * a[r].x + a[r].y * a[r].y;
#pragma unroll
    for (int o = 16; o; o >>= 1) nn += __shfl_xor_sync(0xffffffffu, nn, o);
    const float sc = rsqrtf(nn);
#pragma unroll
    for (int r = 0; r < 32; ++r) { a[r].x *= sc; a[r].y *= sc; }

    apply_circuit_reg(a, sgf, L);

    // per-amp squared norms (reused for all Z measurements)
    float pz[32];
#pragma unroll
    for (int r = 0; r < 32; ++r) pz[r] = a[r].x * a[r].x + a[r].y * a[r].y;

    // measurement: wire w -> bit p = 9-w
#pragma unroll
    for (int wq = 0; wq < NQ; ++wq) {
        const int p = 9 - wq;
        float X = 0.f, Y = 0.f, Z = 0.f;
        if (p >= 5) {
            const int rb = 1 << (p - 5);
#pragma unroll
            for (int r0 = 0; r0 < 32; ++r0) {
                if (!(r0 & rb)) {
                    const int r1 = r0 | rb;
                    X += a[r0].x * a[r1].x + a[r0].y * a[r1].y;
                    Y += a[r0].x * a[r1].y - a[r0].y * a[r1].x;
                    Z += pz[r0] - pz[r1];
                }
            }
            X *= 2.f; Y *= 2.f;
        } else {
            const int lb = 1 << p;
            const float sgn = (L & lb) ? -1.f : 1.f;
#pragma unroll
            for (int r = 0; r < 32; ++r) {
                const float px = __shfl_xor_sync(0xffffffffu, a[r].x, lb);
                const float py = __shfl_xor_sync(0xffffffffu, a[r].y, lb);
                // Re part symmetric: sum over ALL lanes = 2 * sum over pairs
                X += a[r].x * px + a[r].y * py;
                // Im part antisymmetric: fold sign, sum = 2 * sum over pairs
                Y += sgn * (a[r].x * py - a[r].y * px);
                Z += sgn * pz[r];
            }
        }
#pragma unroll
        for (int o = 16; o; o >>= 1) {
            X += __shfl_xor_sync(0xffffffffu, X, o);
            Y += __shfl_xor_sync(0xffffffffu, Y, o);
            Z += __shfl_xor_sync(0xffffffffu, Z, o);
        }
        if (L == 0) {
            out[b * 30 + wq]      = X;
            out[b * 30 + 10 + wq] = Y;
            out[b * 30 + 20 + wq] = Z;
        }
    }
}

// ----------------------------- launch ---------------------------------------
extern "C" void kernel_launch(void* const* d_in, const int* in_sizes, int n_in,
                              void* d_out, int out_size)
{
    const float* tokens = (const float*)d_in[0];  // (128, 32, 512)
    const float* W      = (const float*)d_in[1];  // (40, 512)
    const float* bias   = (const float*)d_in[2];  // (40,)
    const float* lre    = (const float*)d_in[3];  // (32,)
    const float* lim    = (const float*)d_in[4];  // (32,)
    const float* qsvt   = (const float*)d_in[5];  // (3,)
    const float* ffp    = (const float*)d_in[6];  // (40,)
    float* out          = (float*)d_out;          // (128, 30)

    params_kernel<<<NSIM / 8, 256>>>(tokens, W, bias, lre, lim);
    wsim_kernel<true><<<NB * 4, 256>>>();
    wsim_kernel<false><<<NB * 4, 256>>>();
    final_kernel<<<NB / 8, 256>>>(qsvt, ffp, out);
}

// round 10
// speedup vs baseline: 1.5556x; 1.5556x over previous
#include <cuda_runtime.h>
#include <cuda_bf16.h>
#include <math.h>

// Problem constants
#define NQ   10
#define DIM  1024        // 2^NQ
#define NT   32
#define DM   512
#define NB   128         // batch
#define NPQC 40
#define NSIM (NB * NT)   // 4096 statevector sims per pass

// ---------------- device scratch (static globals, no allocation) -------------
__device__ float2 d_part1[(size_t)NB * 4 * DIM]; // pass-1 per-CTA LCU partials (4 MB)
__device__ float2 d_part2[(size_t)NB * 4 * DIM]; // pass-2 per-CTA LCU partials (4 MB)
__device__ float2 d_gt[(size_t)NSIM * NPQC];     // per-(b,l) gate (cos,sin) tables
__device__ float2 d_lcuW[NT];                    // normalized LCU weights

// Gate encoding: bit0 = type (0=RY, 1=CRX); bits[1..4] = RY bit position or
// CRX control position; bits[5..8] = CRX target position.
// Bit position p of qubit wire w is p = 9 - w (reference is big-endian).
#define RYG(p)      ((unsigned)((p) << 1))
#define CXG(cp, tp) ((unsigned)(1u | ((cp) << 1) | ((tp) << 5)))

#define GATE_LIST                                                              \
        RYG(9), RYG(8), RYG(7), RYG(6), RYG(5), RYG(4), RYG(3), RYG(2),        \
        RYG(1), RYG(0),                                                        \
        CXG(0, 9), CXG(1, 0), CXG(2, 1), CXG(3, 2), CXG(4, 3),                 \
        CXG(5, 4), CXG(6, 5), CXG(7, 6), CXG(8, 7), CXG(9, 8),                 \
        RYG(9), RYG(8), RYG(7), RYG(6), RYG(5), RYG(4), RYG(3), RYG(2),        \
        RYG(1), RYG(0),                                                        \
        CXG(0, 1), CXG(9, 0), CXG(8, 9), CXG(7, 8), CXG(6, 7),                 \
        CXG(5, 6), CXG(4, 5), CXG(3, 4), CXG(2, 3), CXG(1, 2)

// ---- register-resident circuit: lane L slot r holds amplitude g = r*32+L ----
//   g bits 5..9 -> register bits (pure-FFMA butterflies)
//   g bits 0..4 -> lane bits (partner via shfl.xor; controls fold into coeffs)
__device__ __forceinline__ void apply_circuit_reg(float2 a[32],
                                                  const float2* __restrict__ g,
                                                  int L)
{
    constexpr unsigned G[NPQC] = { GATE_LIST };
#pragma unroll
    for (int k = 0; k < NPQC; ++k) {
        const unsigned e = G[k];
        const float cth = g[k].x;
        const float sth = g[k].y;
        if (!(e & 1u)) {
            const int p = (int)((e >> 1) & 15u);
            if (p >= 5) {
                // RY on register bit
                const int rb = 1 << (p - 5);
#pragma unroll
                for (int r0 = 0; r0 < 32; ++r0) {
                    if (!(r0 & rb)) {
                        const int r1 = r0 | rb;
                        const float2 a0 = a[r0], a1 = a[r1];
                        a[r0] = make_float2(cth * a0.x - sth * a1.x,
                                            cth * a0.y - sth * a1.y);
                        a[r1] = make_float2(sth * a0.x + cth * a1.x,
                                            sth * a0.y + cth * a1.y);
                    }
                }
            } else {
                // RY on lane bit: a' = c*a + se*partner, se = bit? +s : -s
                const int lb = 1 << p;
                const float se = (L & lb) ? sth : -sth;
#pragma unroll
                for (int r = 0; r < 32; ++r) {
                    const float px = __shfl_xor_sync(0xffffffffu, a[r].x, lb);
                    const float py = __shfl_xor_sync(0xffffffffu, a[r].y, lb);
                    a[r] = make_float2(cth * a[r].x + se * px,
                                       cth * a[r].y + se * py);
                }
            }
        } else {
            const int cp = (int)((e >> 1) & 15u);
            const int tp = (int)((e >> 5) & 15u);
            if (tp >= 5) {
                const int rb = 1 << (tp - 5);
                if (cp >= 5) {
                    // control is a register bit: folds at compile time
                    const int cb = 1 << (cp - 5);
#pragma unroll
                    for (int r0 = 0; r0 < 32; ++r0) {
                        if (!(r0 & rb) && (r0 & cb)) {
                            const int r1 = r0 | rb;
                            const float2 a0 = a[r0], a1 = a[r1];
                            a[r0] = make_float2(cth * a0.x + sth * a1.y,
                                                cth * a0.y - sth * a1.x);
                            a[r1] = make_float2(sth * a0.y + cth * a1.x,
                                                cth * a1.y - sth * a0.x);
                        }
                    }
                } else {
                    // lane-bit control folded into coefficients
                    const bool act = (L >> cp) & 1;
                    const float ce = act ? cth : 1.f;
                    const float se = act ? sth : 0.f;
#pragma unroll
                    for (int r0 = 0; r0 < 32; ++r0) {
                        if (!(r0 & rb)) {
                            const int r1 = r0 | rb;
                            const float2 a0 = a[r0], a1 = a[r1];
                            a[r0] = make_float2(ce * a0.x + se * a1.y,
                                                ce * a0.y - se * a1.x);
                            a[r1] = make_float2(se * a0.y + ce * a1.x,
                                                ce * a1.y - se * a0.x);
                        }
                    }
                }
            } else {
                // RX on lane bit: a' = (c*ax + s*py, c*ay - s*px)
                const int lb = 1 << tp;
                if (cp >= 5) {
                    const int cb = 1 << (cp - 5);
#pragma unroll
                    for (int r = 0; r < 32; ++r) {
                        if (r & cb) {
                            const float px = __shfl_xor_sync(0xffffffffu, a[r].x, lb);
                            const float py = __shfl_xor_sync(0xffffffffu, a[r].y, lb);
                            a[r] = make_float2(cth * a[r].x + sth * py,
                                               cth * a[r].y - sth * px);
                        }
                    }
                } else {
                    const bool act = (L >> cp) & 1;
                    const float ce = act ? cth : 1.f;
                    const float se = act ? sth : 0.f;
#pragma unroll
                    for (int r = 0; r < 32; ++r) {
                        const float px = __shfl_xor_sync(0xffffffffu, a[r].x, lb);
                        const float py = __shfl_xor_sync(0xffffffffu, a[r].y, lb);
                        a[r] = make_float2(ce * a[r].x + se * py,
                                           ce * a[r].y - se * px);
                    }
                }
            }
        }
    }
}

// ----------------------------- kernels --------------------------------------

// pqc_params = tokens @ W.T + b -> (cos, sin) of theta/2 per gate.
// One block per (b,l) row; 256 threads; float4-vectorized dots. (R7-verified.)
// Block 0 additionally computes the normalized LCU weights (warp 0).
__global__ void params_kernel(const float* __restrict__ tokens,
                              const float* __restrict__ W,
                              const float* __restrict__ bias,
                              const float* __restrict__ lre,
                              const float* __restrict__ lim)
{
    const int blk = blockIdx.x;                 // b*32 + l
    const int tid = threadIdx.x;

    if (blk == 0 && tid < 32) {
        const float r = lre[tid], i = lim[tid];
        const float a = sqrtf(r * r + i * i);
        float ssum = a;
#pragma unroll
        for (int o = 16; o; o >>= 1) ssum += __shfl_xor_sync(0xffffffffu, ssum, o);
        d_lcuW[tid] = make_float2(r / ssum, i / ssum);
    }

    __shared__ float4 sh4[DM / 4];              // 128 float4 = 512 floats
    const float4* row4 = (const float4*)(tokens + (size_t)blk * DM);
    if (tid < DM / 4) sh4[tid] = row4[tid];
    __syncthreads();

    const int warp = tid >> 5;
    const int lane = tid & 31;
    for (int k = warp; k < NPQC; k += 8) {
        const float4* w4 = (const float4*)(W + (size_t)k * DM);
        float acc = 0.f;
#pragma unroll
        for (int j = 0; j < 4; ++j) {
            const int idx = lane + j * 32;
            const float4 t = sh4[idx];
            const float4 ww = __ldg(w4 + idx);
            acc += t.x * ww.x + t.y * ww.y + t.z * ww.z + t.w * ww.w;
        }
#pragma unroll
        for (int o = 16; o; o >>= 1) acc += __shfl_xor_sync(0xffffffffu, acc, o);
        if (lane == 0) {
            const float h = 0.5f * (acc + __ldg(bias + k));
            d_gt[(size_t)blk * NPQC + k] = make_float2(cosf(h), sinf(h));
        }
    }
}

// Warp-per-statevector simulator. One CTA = 8 warps = 8 consecutive l-values
// of one batch. Pass 2 rebuilds the monomial state from the 4 pass-1 partials
// (smem-staged, summed once per CTA). The LCU-weighted sum over the CTA's 8
// l's is reduced in smem and written to the pass's partial buffer.
template <bool FIRST>
__global__ void __launch_bounds__(256, 2) wsim_kernel()
{
    const int blk = blockIdx.x;          // b*4 + c
    const int b   = blk >> 2;
    const int c   = blk & 3;
    const int tid = threadIdx.x;         // 256
    const int w   = tid >> 5;            // warp 0..7
    const int L   = tid & 31;
    const int l   = c * 8 + w;

    __shared__ float2 sg[8][NPQC];       // gate tables (2.5 KB)
    __shared__ float2 sbuf[4][DIM];      // staging / reduction slots (32 KB)

    // Load 8 gate tables (contiguous in d_gt) cooperatively.
    {
        const float2* gbase = d_gt + ((size_t)(b * NT + c * 8)) * NPQC;
        for (int i = tid; i < 8 * NPQC; i += 256)
            (&sg[0][0])[i] = gbase[i];
    }

    if (!FIRST) {
        // mono = sum of the batch's 4 pass-1 partials; stage in sbuf[0].
        for (int g = tid; g < DIM; g += 256) {
            float2 m = d_part1[(size_t)(b * 4 + 0) * DIM + g];
#pragma unroll
            for (int cc = 1; cc < 4; ++cc) {
                const float2 v = d_part1[(size_t)(b * 4 + cc) * DIM + g];
                m.x += v.x; m.y += v.y;
            }
            sbuf[0][g] = m;
        }
    }
    __syncthreads();

    float2 a[32];
    if (FIRST) {
#pragma unroll
        for (int r = 0; r < 32; ++r) a[r] = make_float2(0.f, 0.f);
        a[0].x = (L == 0) ? 1.f : 0.f;
    } else {
#pragma unroll
        for (int r = 0; r < 32; ++r) a[r] = sbuf[0][r * 32 + L];
    }
    __syncthreads();   // sbuf[0] reads complete before epilogue reuses sbuf

    apply_circuit_reg(a, sg[w], L);

    // ---- LCU weight + in-CTA reduction over the 8 warps --------------------
    const float2 wl = d_lcuW[l];
#pragma unroll
    for (int r = 0; r < 32; ++r) {
        const float2 v = a[r];
        a[r] = make_float2(wl.x * v.x - wl.y * v.y,
                           wl.x * v.y + wl.y * v.x);
    }
    // stage 1: warps 0-3 write their weighted state to slot w
    if (w < 4) {
#pragma unroll
        for (int r = 0; r < 32; ++r) sbuf[w][r * 32 + L] = a[r];
    }
    __syncthreads();
    // stage 2: warps 4-7 add into slot w-4
    if (w >= 4) {
        const int slot = w - 4;
#pragma unroll
        for (int r = 0; r < 32; ++r) {
            float2 v = sbuf[slot][r * 32 + L];
            v.x += a[r].x; v.y += a[r].y;
            sbuf[slot][r * 32 + L] = v;
        }
    }
    __syncthreads();
    // stage 3: 256 threads reduce the 4 slots, write the CTA partial
    float2* outp = (FIRST ? d_part1 : d_part2) + (size_t)blk * DIM;
#pragma unroll
    for (int j = 0; j < 4; ++j) {
        const int g = tid + j * 256;
        float2 m = sbuf[0][g];
#pragma unroll
        for (int wi = 1; wi < 4; ++wi) {
            m.x += sbuf[wi][g].x;
            m.y += sbuf[wi][g].y;
        }
        outp[g] = m;
    }
}

// Warp-per-batch final stage: QSVT-combine partials into a register state,
// normalize, apply feed-forward ansatz, measure X/Y/Z.
// 128 CTAs x 32 threads (one warp per batch, spread across the chip).
// No pz[] array and no launch-bounds cap -> no register spill.
__global__ void final_kernel(const float* __restrict__ qsvt,
                             const float* __restrict__ ffp,
                             float* __restrict__ out)
{
    const int L = threadIdx.x;                   // 32 threads = 1 warp
    const int b = blockIdx.x;                    // batch index, 0..127

    __shared__ float2 sgf[NPQC];                 // feed-forward gate table
    if (L < NPQC - 32) {
        const float h = 0.5f * ffp[L + 32];
        sgf[L + 32] = make_float2(cosf(h), sinf(h));
    }
    {
        const float h = 0.5f * ffp[L];
        sgf[L] = make_float2(cosf(h), sinf(h));
    }
    __syncwarp();

    const float c0 = qsvt[0], c1 = qsvt[1], c2 = qsvt[2];

    // QSVT accumulator in registers (scale 1/sum|qsvt| cancels in normalize)
    float2 a[32];
#pragma unroll
    for (int r = 0; r < 32; ++r) {
        const int g = r * 32 + L;
        float2 m1 = make_float2(0.f, 0.f), m2 = make_float2(0.f, 0.f);
#pragma unroll
        for (int c = 0; c < 4; ++c) {
            const size_t base = (size_t)(b * 4 + c) * DIM + g;
            const float2 v1 = d_part1[base];
            const float2 v2 = d_part2[base];
            m1.x += v1.x; m1.y += v1.y;
            m2.x += v2.x; m2.y += v2.y;
        }
        a[r] = make_float2(c1 * m1.x + c2 * m2.x, c1 * m1.y + c2 * m2.y);
    }
    if (L == 0) a[0].x += c0;

    // in-warp L2 normalization
    float nn = 0.f;
#pragma unroll
    for (int r = 0; r < 32; ++r) nn += a[r].x * a[r].x + a[r].y * a[r].y;
#pragma unroll
    for (int o = 16; o; o >>= 1) nn += __shfl_xor_sync(0xffffffffu, nn, o);
    const float sc = rsqrtf(nn);
#pragma unroll
    for (int r = 0; r < 32; ++r) { a[r].x *= sc; a[r].y *= sc; }

    apply_circuit_reg(a, sgf, L);

    // measurement: wire w -> bit p = 9-w. |a|^2 recomputed inline (no pz[]).
#pragma unroll
    for (int wq = 0; wq < NQ; ++wq) {
        const int p = 9 - wq;
        float X = 0.f, Y = 0.f, Z = 0.f;
        if (p >= 5) {
            const int rb = 1 << (p - 5);
#pragma unroll
            for (int r0 = 0; r0 < 32; ++r0) {
                if (!(r0 & rb)) {
                    const int r1 = r0 | rb;
                    X += a[r0].x * a[r1].x + a[r0].y * a[r1].y;
                    Y += a[r0].x * a[r1].y - a[r0].y * a[r1].x;
                    Z += (a[r0].x * a[r0].x + a[r0].y * a[r0].y)
                       - (a[r1].x * a[r1].x + a[r1].y * a[r1].y);
                }
            }
            X *= 2.f; Y *= 2.f;
        } else {
            const int lb = 1 << p;
            const float sgn = (L & lb) ? -1.f : 1.f;
#pragma unroll
            for (int r = 0; r < 32; ++r) {
                const float px = __shfl_xor_sync(0xffffffffu, a[r].x, lb);
                const float py = __shfl_xor_sync(0xffffffffu, a[r].y, lb);
                // Re part symmetric: sum over ALL lanes = 2 * sum over pairs
                X += a[r].x * px + a[r].y * py;
                // Im part antisymmetric: fold sign, sum = 2 * sum over pairs
                Y += sgn * (a[r].x * py - a[r].y * px);
                Z += sgn * (a[r].x * a[r].x + a[r].y * a[r].y);
            }
        }
#pragma unroll
        for (int o = 16; o; o >>= 1) {
            X += __shfl_xor_sync(0xffffffffu, X, o);
            Y += __shfl_xor_sync(0xffffffffu, Y, o);
            Z += __shfl_xor_sync(0xffffffffu, Z, o);
        }
        if (L == 0) {
            out[b * 30 + wq]      = X;
            out[b * 30 + 10 + wq] = Y;
            out[b * 30 + 20 + wq] = Z;
        }
    }
}

// ----------------------------- launch ---------------------------------------
extern "C" void kernel_launch(void* const* d_in, const int* in_sizes, int n_in,
                              void* d_out, int out_size)
{
    const float* tokens = (const float*)d_in[0];  // (128, 32, 512)
    const float* W      = (const float*)d_in[1];  // (40, 512)
    const float* bias   = (const float*)d_in[2];  // (40,)
    const float* lre    = (const float*)d_in[3];  // (32,)
    const float* lim    = (const float*)d_in[4];  // (32,)
    const float* qsvt   = (const float*)d_in[5];  // (3,)
    const float* ffp    = (const float*)d_in[6];  // (40,)
    float* out          = (float*)d_out;          // (128, 30)

    params_kernel<<<NSIM, 256>>>(tokens, W, bias, lre, lim);
    wsim_kernel<true><<<NB * 4, 256>>>();
    wsim_kernel<false><<<NB * 4, 256>>>();
    final_kernel<<<NB, 32>>>(qsvt, ffp, out);
}

// round 11
// speedup vs baseline: 1.7565x; 1.1291x over previous
#include <cuda_runtime.h>
#include <cuda_bf16.h>
#include <math.h>

// Problem constants
#define NQ   10
#define DIM  1024        // 2^NQ
#define NT   32
#define DM   512
#define NB   128         // batch
#define NPQC 40
#define NSIM (NB * NT)   // 4096 statevector sims per pass

// ---------------- device scratch (static globals, no allocation) -------------
__device__ float2 d_part1[(size_t)NB * 4 * DIM]; // pass-1 per-CTA LCU partials (4 MB)
__device__ float2 d_part2[(size_t)NB * 4 * DIM]; // pass-2 per-CTA LCU partials (4 MB)
__device__ float2 d_gt[(size_t)NSIM * NPQC];     // per-(b,l) gate (cos,sin) tables
__device__ float2 d_lcuW[NT];                    // normalized LCU weights

// Gate encoding: bit0 = type (0=RY, 1=CRX); bits[1..4] = RY bit position or
// CRX control position; bits[5..8] = CRX target position.
// Bit position p of qubit wire w is p = 9 - w (reference is big-endian).
#define RYG(p)      ((unsigned)((p) << 1))
#define CXG(cp, tp) ((unsigned)(1u | ((cp) << 1) | ((tp) << 5)))

#define GATE_LIST                                                              \
        RYG(9), RYG(8), RYG(7), RYG(6), RYG(5), RYG(4), RYG(3), RYG(2),        \
        RYG(1), RYG(0),                                                        \
        CXG(0, 9), CXG(1, 0), CXG(2, 1), CXG(3, 2), CXG(4, 3),                 \
        CXG(5, 4), CXG(6, 5), CXG(7, 6), CXG(8, 7), CXG(9, 8),                 \
        RYG(9), RYG(8), RYG(7), RYG(6), RYG(5), RYG(4), RYG(3), RYG(2),        \
        RYG(1), RYG(0),                                                        \
        CXG(0, 1), CXG(9, 0), CXG(8, 9), CXG(7, 8), CXG(6, 7),                 \
        CXG(5, 6), CXG(4, 5), CXG(3, 4), CXG(2, 3), CXG(1, 2)

// ---- register-resident circuit: lane L slot r holds amplitude g = r*32+L ----
//   g bits 5..9 -> register bits (pure-FFMA butterflies)
//   g bits 0..4 -> lane bits (partner via shfl.xor; controls fold into coeffs)
__device__ __forceinline__ void apply_circuit_reg(float2 a[32],
                                                  const float2* __restrict__ g,
                                                  int L)
{
    constexpr unsigned G[NPQC] = { GATE_LIST };
#pragma unroll
    for (int k = 0; k < NPQC; ++k) {
        const unsigned e = G[k];
        const float cth = g[k].x;
        const float sth = g[k].y;
        if (!(e & 1u)) {
            const int p = (int)((e >> 1) & 15u);
            if (p >= 5) {
                // RY on register bit
                const int rb = 1 << (p - 5);
#pragma unroll
                for (int r0 = 0; r0 < 32; ++r0) {
                    if (!(r0 & rb)) {
                        const int r1 = r0 | rb;
                        const float2 a0 = a[r0], a1 = a[r1];
                        a[r0] = make_float2(cth * a0.x - sth * a1.x,
                                            cth * a0.y - sth * a1.y);
                        a[r1] = make_float2(sth * a0.x + cth * a1.x,
                                            sth * a0.y + cth * a1.y);
                    }
                }
            } else {
                // RY on lane bit: a' = c*a + se*partner, se = bit? +s : -s
                const int lb = 1 << p;
                const float se = (L & lb) ? sth : -sth;
#pragma unroll
                for (int r = 0; r < 32; ++r) {
                    const float px = __shfl_xor_sync(0xffffffffu, a[r].x, lb);
                    const float py = __shfl_xor_sync(0xffffffffu, a[r].y, lb);
                    a[r] = make_float2(cth * a[r].x + se * px,
                                       cth * a[r].y + se * py);
                }
            }
        } else {
            const int cp = (int)((e >> 1) & 15u);
            const int tp = (int)((e >> 5) & 15u);
            if (tp >= 5) {
                const int rb = 1 << (tp - 5);
                if (cp >= 5) {
                    // control is a register bit: folds at compile time
                    const int cb = 1 << (cp - 5);
#pragma unroll
                    for (int r0 = 0; r0 < 32; ++r0) {
                        if (!(r0 & rb) && (r0 & cb)) {
                            const int r1 = r0 | rb;
                            const float2 a0 = a[r0], a1 = a[r1];
                            a[r0] = make_float2(cth * a0.x + sth * a1.y,
                                                cth * a0.y - sth * a1.x);
                            a[r1] = make_float2(sth * a0.y + cth * a1.x,
                                                cth * a1.y - sth * a0.x);
                        }
                    }
                } else {
                    // lane-bit control folded into coefficients
                    const bool act = (L >> cp) & 1;
                    const float ce = act ? cth : 1.f;
                    const float se = act ? sth : 0.f;
#pragma unroll
                    for (int r0 = 0; r0 < 32; ++r0) {
                        if (!(r0 & rb)) {
                            const int r1 = r0 | rb;
                            const float2 a0 = a[r0], a1 = a[r1];
                            a[r0] = make_float2(ce * a0.x + se * a1.y,
                                                ce * a0.y - se * a1.x);
                            a[r1] = make_float2(se * a0.y + ce * a1.x,
                                                ce * a1.y - se * a0.x);
                        }
                    }
                }
            } else {
                // RX on lane bit: a' = (c*ax + s*py, c*ay - s*px)
                const int lb = 1 << tp;
                if (cp >= 5) {
                    const int cb = 1 << (cp - 5);
#pragma unroll
                    for (int r = 0; r < 32; ++r) {
                        if (r & cb) {
                            const float px = __shfl_xor_sync(0xffffffffu, a[r].x, lb);
                            const float py = __shfl_xor_sync(0xffffffffu, a[r].y, lb);
                            a[r] = make_float2(cth * a[r].x + sth * py,
                                               cth * a[r].y - sth * px);
                        }
                    }
                } else {
                    const bool act = (L >> cp) & 1;
                    const float ce = act ? cth : 1.f;
                    const float se = act ? sth : 0.f;
#pragma unroll
                    for (int r = 0; r < 32; ++r) {
                        const float px = __shfl_xor_sync(0xffffffffu, a[r].x, lb);
                        const float py = __shfl_xor_sync(0xffffffffu, a[r].y, lb);
                        a[r] = make_float2(ce * a[r].x + se * py,
                                           ce * a[r].y - se * px);
                    }
                }
            }
        }
    }
}

// ----------------------------- kernels --------------------------------------

// pqc_params = tokens @ W.T + b -> (cos, sin) of theta/2 per gate.
// One block per (b,l) row; 256 threads; float4-vectorized dots. (R7-verified.)
// Block 0 additionally computes the normalized LCU weights (warp 0).
__global__ void params_kernel(const float* __restrict__ tokens,
                              const float* __restrict__ W,
                              const float* __restrict__ bias,
                              const float* __restrict__ lre,
                              const float* __restrict__ lim)
{
    const int blk = blockIdx.x;                 // b*32 + l
    const int tid = threadIdx.x;

    if (blk == 0 && tid < 32) {
        const float r = lre[tid], i = lim[tid];
        const float a = sqrtf(r * r + i * i);
        float ssum = a;
#pragma unroll
        for (int o = 16; o; o >>= 1) ssum += __shfl_xor_sync(0xffffffffu, ssum, o);
        d_lcuW[tid] = make_float2(r / ssum, i / ssum);
    }

    __shared__ float4 sh4[DM / 4];              // 128 float4 = 512 floats
    const float4* row4 = (const float4*)(tokens + (size_t)blk * DM);
    if (tid < DM / 4) sh4[tid] = row4[tid];
    __syncthreads();

    const int warp = tid >> 5;
    const int lane = tid & 31;
    for (int k = warp; k < NPQC; k += 8) {
        const float4* w4 = (const float4*)(W + (size_t)k * DM);
        float acc = 0.f;
#pragma unroll
        for (int j = 0; j < 4; ++j) {
            const int idx = lane + j * 32;
            const float4 t = sh4[idx];
            const float4 ww = __ldg(w4 + idx);
            acc += t.x * ww.x + t.y * ww.y + t.z * ww.z + t.w * ww.w;
        }
#pragma unroll
        for (int o = 16; o; o >>= 1) acc += __shfl_xor_sync(0xffffffffu, acc, o);
        if (lane == 0) {
            const float h = 0.5f * (acc + __ldg(bias + k));
            d_gt[(size_t)blk * NPQC + k] = make_float2(cosf(h), sinf(h));
        }
    }
}

// Warp-per-statevector simulator. One CTA = 8 warps = 8 consecutive l-values
// of one batch. Pass 2 rebuilds the monomial state from the 4 pass-1 partials
// (smem-staged, summed once per CTA). The LCU-weighted sum over the CTA's 8
// l's is reduced in smem and written to the pass's partial buffer.
template <bool FIRST>
__global__ void __launch_bounds__(256, 2) wsim_kernel()
{
    const int blk = blockIdx.x;          // b*4 + c
    const int b   = blk >> 2;
    const int c   = blk & 3;
    const int tid = threadIdx.x;         // 256
    const int w   = tid >> 5;            // warp 0..7
    const int L   = tid & 31;
    const int l   = c * 8 + w;

    __shared__ float2 sg[8][NPQC];       // gate tables (2.5 KB)
    __shared__ float2 sbuf[4][DIM];      // staging / reduction slots (32 KB)

    // Load 8 gate tables (contiguous in d_gt) cooperatively.
    {
        const float2* gbase = d_gt + ((size_t)(b * NT + c * 8)) * NPQC;
        for (int i = tid; i < 8 * NPQC; i += 256)
            (&sg[0][0])[i] = gbase[i];
    }

    if (!FIRST) {
        // mono = sum of the batch's 4 pass-1 partials; stage in sbuf[0].
        for (int g = tid; g < DIM; g += 256) {
            float2 m = d_part1[(size_t)(b * 4 + 0) * DIM + g];
#pragma unroll
            for (int cc = 1; cc < 4; ++cc) {
                const float2 v = d_part1[(size_t)(b * 4 + cc) * DIM + g];
                m.x += v.x; m.y += v.y;
            }
            sbuf[0][g] = m;
        }
    }
    __syncthreads();

    float2 a[32];
    if (FIRST) {
#pragma unroll
        for (int r = 0; r < 32; ++r) a[r] = make_float2(0.f, 0.f);
        a[0].x = (L == 0) ? 1.f : 0.f;
    } else {
#pragma unroll
        for (int r = 0; r < 32; ++r) a[r] = sbuf[0][r * 32 + L];
    }
    __syncthreads();   // sbuf[0] reads complete before epilogue reuses sbuf

    apply_circuit_reg(a, sg[w], L);

    // ---- LCU weight + in-CTA reduction over the 8 warps --------------------
    const float2 wl = d_lcuW[l];
#pragma unroll
    for (int r = 0; r < 32; ++r) {
        const float2 v = a[r];
        a[r] = make_float2(wl.x * v.x - wl.y * v.y,
                           wl.x * v.y + wl.y * v.x);
    }
    // stage 1: warps 0-3 write their weighted state to slot w
    if (w < 4) {
#pragma unroll
        for (int r = 0; r < 32; ++r) sbuf[w][r * 32 + L] = a[r];
    }
    __syncthreads();
    // stage 2: warps 4-7 add into slot w-4
    if (w >= 4) {
        const int slot = w - 4;
#pragma unroll
        for (int r = 0; r < 32; ++r) {
            float2 v = sbuf[slot][r * 32 + L];
            v.x += a[r].x; v.y += a[r].y;
            sbuf[slot][r * 32 + L] = v;
        }
    }
    __syncthreads();
    // stage 3: 256 threads reduce the 4 slots, write the CTA partial
    float2* outp = (FIRST ? d_part1 : d_part2) + (size_t)blk * DIM;
#pragma unroll
    for (int j = 0; j < 4; ++j) {
        const int g = tid + j * 256;
        float2 m = sbuf[0][g];
#pragma unroll
        for (int wi = 1; wi < 4; ++wi) {
            m.x += sbuf[wi][g].x;
            m.y += sbuf[wi][g].y;
        }
        outp[g] = m;
    }
}

// -------- shared-memory circuit (used only by final_kernel, 128 CTAs) -------
__device__ __forceinline__ void apply_circuit_smem(float2* s, const float2* g, int tid)
{
    const unsigned G[NPQC] = { GATE_LIST };
#pragma unroll
    for (int k = 0; k < NPQC; ++k) {
        const unsigned e = G[k];
        const float c  = g[k].x;
        const float sn = g[k].y;
        if (!(e & 1u)) {
            const int p   = (int)((e >> 1) & 15u);
            const int bit = 1 << p;
            const int low = tid & (bit - 1);
            const int i0  = ((tid >> p) << (p + 1)) | low;
            const int i1  = i0 | bit;
            const float2 a0 = s[i0];
            const float2 a1 = s[i1];
            s[i0] = make_float2(c * a0.x - sn * a1.x, c * a0.y - sn * a1.y);
            s[i1] = make_float2(sn * a0.x + c * a1.x, sn * a0.y + c * a1.y);
        } else if (tid < 256) {
            const int cp = (int)((e >> 1) & 15u);
            const int tp = (int)((e >> 5) & 15u);
            const int pl = (cp < tp) ? cp : tp;
            const int ph = cp ^ tp ^ pl;
            const int bl = 1 << pl;
            const int bh = 1 << ph;
            const int low1 = tid & (bl - 1);
            const int t1   = ((tid >> pl) << (pl + 1)) | low1;
            const int low2 = t1 & (bh - 1);
            const int idx  = ((t1 >> ph) << (ph + 1)) | low2;
            const int i0   = idx | (1 << cp);
            const int i1   = i0 | (1 << tp);
            const float2 a0 = s[i0];
            const float2 a1 = s[i1];
            s[i0] = make_float2(c * a0.x + sn * a1.y, c * a0.y - sn * a1.x);
            s[i1] = make_float2(sn * a0.y + c * a1.x, c * a1.y - sn * a0.x);
        }
        __syncthreads();
    }
}

// Build QSVT accumulator from the 8 partials, normalize, apply feed-forward
// ansatz, measure X/Y/Z on all 10 wires. (R7-verified smem version.)
__global__ void __launch_bounds__(512) final_kernel(const float* __restrict__ qsvt,
                                                    const float* __restrict__ ffp,
                                                    float* __restrict__ out)
{
    const int b   = blockIdx.x;
    const int tid = threadIdx.x;         // 512

    __shared__ float2 s[DIM];
    __shared__ float2 g[NPQC];
    __shared__ float redx[16], redy[16], redz[16];

    const float c0 = qsvt[0], c1 = qsvt[1], c2 = qsvt[2];

    float2 a0, a1;
    {
        float2 m1a = make_float2(0.f, 0.f), m2a = make_float2(0.f, 0.f);
        float2 m1b = make_float2(0.f, 0.f), m2b = make_float2(0.f, 0.f);
#pragma unroll
        for (int c = 0; c < 4; ++c) {
            const size_t base = (size_t)(b * 4 + c) * DIM;
            float2 v;
            v = d_part1[base + tid];       m1a.x += v.x; m1a.y += v.y;
            v = d_part2[base + tid];       m2a.x += v.x; m2a.y += v.y;
            v = d_part1[base + tid + 512]; m1b.x += v.x; m1b.y += v.y;
            v = d_part2[base + tid + 512]; m2b.x += v.x; m2b.y += v.y;
        }
        a0 = make_float2(c1 * m1a.x + c2 * m2a.x + (tid == 0 ? c0 : 0.f),
                         c1 * m1a.y + c2 * m2a.y);
        a1 = make_float2(c1 * m1b.x + c2 * m2b.x,
                         c1 * m1b.y + c2 * m2b.y);
    }

    if (tid < NPQC) {
        const float h = 0.5f * ffp[tid];
        g[tid] = make_float2(cosf(h), sinf(h));
    }

    // L2 norm (constant QSVT scale cancels in normalization)
    float nn = a0.x * a0.x + a0.y * a0.y + a1.x * a1.x + a1.y * a1.y;
#pragma unroll
    for (int o = 16; o; o >>= 1) nn += __shfl_xor_sync(0xffffffffu, nn, o);
    if ((tid & 31) == 0) redx[tid >> 5] = nn;
    __syncthreads();
    if (tid < 32) {
        float v = (tid < 16) ? redx[tid] : 0.f;
#pragma unroll
        for (int o = 8; o; o >>= 1) v += __shfl_xor_sync(0xffffffffu, v, o);
        if (tid == 0) redx[0] = rsqrtf(v);
    }
    __syncthreads();
    const float sc = redx[0];
    s[tid]       = make_float2(a0.x * sc, a0.y * sc);
    s[tid + 512] = make_float2(a1.x * sc, a1.y * sc);
    __syncthreads();

    apply_circuit_smem(s, g, tid);

    // measurement: per wire w, pairs split on bit p = 9-w
#pragma unroll
    for (int w = 0; w < NQ; ++w) {
        const int p   = 9 - w;
        const int bit = 1 << p;
        const int low = tid & (bit - 1);
        const int i0  = ((tid >> p) << (p + 1)) | low;
        const int i1  = i0 | bit;
        const float2 v0 = s[i0];
        const float2 v1 = s[i1];
        float xr = v0.x * v1.x + v0.y * v1.y;             // Re(conj(a0)*a1)
        float yi = v0.x * v1.y - v0.y * v1.x;             // Im(conj(a0)*a1)
        float zz = v0.x * v0.x + v0.y * v0.y - v1.x * v1.x - v1.y * v1.y;
#pragma unroll
        for (int o = 16; o; o >>= 1) {
            xr += __shfl_xor_sync(0xffffffffu, xr, o);
            yi += __shfl_xor_sync(0xffffffffu, yi, o);
            zz += __shfl_xor_sync(0xffffffffu, zz, o);
        }
        __syncthreads();
        if ((tid & 31) == 0) {
            redx[tid >> 5] = xr; redy[tid >> 5] = yi; redz[tid >> 5] = zz;
        }
        __syncthreads();
        if (tid < 32) {
            float vx = (tid < 16) ? redx[tid] : 0.f;
            float vy = (tid < 16) ? redy[tid] : 0.f;
            float vz = (tid < 16) ? redz[tid] : 0.f;
#pragma unroll
            for (int o = 8; o; o >>= 1) {
                vx += __shfl_xor_sync(0xffffffffu, vx, o);
                vy += __shfl_xor_sync(0xffffffffu, vy, o);
                vz += __shfl_xor_sync(0xffffffffu, vz, o);
            }
            if (tid == 0) {
                out[b * 30 + w]      = 2.f * vx;
                out[b * 30 + 10 + w] = 2.f * vy;
                out[b * 30 + 20 + w] = vz;
            }
        }
    }
}

// ----------------------------- launch ---------------------------------------
extern "C" void kernel_launch(void* const* d_in, const int* in_sizes, int n_in,
                              void* d_out, int out_size)
{
    const float* tokens = (const float*)d_in[0];  // (128, 32, 512)
    const float* W      = (const float*)d_in[1];  // (40, 512)
    const float* bias   = (const float*)d_in[2];  // (40,)
    const float* lre    = (const float*)d_in[3];  // (32,)
    const float* lim    = (const float*)d_in[4];  // (32,)
    const float* qsvt   = (const float*)d_in[5];  // (3,)
    const float* ffp    = (const float*)d_in[6];  // (40,)
    float* out          = (float*)d_out;          // (128, 30)

    params_kernel<<<NSIM, 256>>>(tokens, W, bias, lre, lim);
    wsim_kernel<true><<<NB * 4, 256>>>();
    wsim_kernel<false><<<NB * 4, 256>>>();
    final_kernel<<<NB, 512>>>(qsvt, ffp, out);
}